// round 15
// baseline (speedup 1.0000x reference)
#include <cuda_runtime.h>
#include <stdint.h>

#define N_NODES 100000
#define N_EDGES 600000
#define NODE_IN 387
#define HID 128
#define EDGE_DIM 7
#define EIN 263  // 2*HID + EDGE_DIM

// -------- scratch (device globals; no allocation allowed) --------
__device__ float g_agg1[(size_t)N_NODES * NODE_IN];  // 154.8 MB
__device__ float g_t   [(size_t)N_NODES * HID];      // 51.2 MB
__device__ float g_h1  [(size_t)N_NODES * HID];
__device__ float g_agg2[(size_t)N_NODES * HID];
__device__ float g_h2  [(size_t)N_NODES * HID];
__device__ int   g_is64;  // 1 if edge_index is int64, 0 if int32

// Detect edge_index dtype from data: int64 words are valid indices < N_NODES;
// int32 data read as int64 packs two indices and exceeds N_NODES w.h.p.
__global__ void detect_idx_kernel(const long long* __restrict__ ei)
{
    if (threadIdx.x == 0 && blockIdx.x == 0) {
        int is64 = 1;
        #pragma unroll
        for (int i = 0; i < 16; i++) {
            long long v = ei[i];
            if (v < 0 || v >= (long long)N_NODES) is64 = 0;
        }
        g_is64 = is64;
    }
}

__device__ __forceinline__ void load_edge(const void* ei, int e, int is64, int& s, int& dd)
{
    if (is64) {
        const long long* p = (const long long*)ei;
        s  = (int)__ldg(&p[e]);
        dd = (int)__ldg(&p[N_EDGES + e]);
    } else {
        const int* p = (const int*)ei;
        s  = __ldg(&p[e]);
        dd = __ldg(&p[N_EDGES + e]);
    }
}

// ================= conv1 edge messages: agg1[dst] += relu(x[src] + ea @ e1_w + e1_b)
__global__ __launch_bounds__(256) void edge_msg1_kernel(
    const float* __restrict__ x, const void* __restrict__ ei,
    const float* __restrict__ ea, const float* __restrict__ w,
    const float* __restrict__ b)
{
    __shared__ float sw[EDGE_DIM * NODE_IN];
    __shared__ float sb[NODE_IN];
    for (int i = threadIdx.x; i < EDGE_DIM * NODE_IN; i += blockDim.x) sw[i] = w[i];
    for (int i = threadIdx.x; i < NODE_IN; i += blockDim.x) sb[i] = b[i];
    __syncthreads();

    int is64   = g_is64;
    int lane   = threadIdx.x & 31;
    int warp   = (blockIdx.x * blockDim.x + threadIdx.x) >> 5;
    int nwarps = (gridDim.x * blockDim.x) >> 5;

    for (int e = warp; e < N_EDGES; e += nwarps) {
        int s, dd;
        load_edge(ei, e, is64, s, dd);
        float eav = (lane < EDGE_DIM) ? __ldg(&ea[(size_t)e * EDGE_DIM + lane]) : 0.0f;
        float a0 = __shfl_sync(0xffffffffu, eav, 0);
        float a1 = __shfl_sync(0xffffffffu, eav, 1);
        float a2 = __shfl_sync(0xffffffffu, eav, 2);
        float a3 = __shfl_sync(0xffffffffu, eav, 3);
        float a4 = __shfl_sync(0xffffffffu, eav, 4);
        float a5 = __shfl_sync(0xffffffffu, eav, 5);
        float a6 = __shfl_sync(0xffffffffu, eav, 6);
        const float* xr = x + (size_t)s * NODE_IN;
        float* ag = g_agg1 + (size_t)dd * NODE_IN;
        #pragma unroll 4
        for (int j = lane; j < NODE_IN; j += 32) {
            float c = sb[j];
            c = fmaf(a0, sw[0 * NODE_IN + j], c);
            c = fmaf(a1, sw[1 * NODE_IN + j], c);
            c = fmaf(a2, sw[2 * NODE_IN + j], c);
            c = fmaf(a3, sw[3 * NODE_IN + j], c);
            c = fmaf(a4, sw[4 * NODE_IN + j], c);
            c = fmaf(a5, sw[5 * NODE_IN + j], c);
            c = fmaf(a6, sw[6 * NODE_IN + j], c);
            float m = fmaxf(__ldg(xr + j) + c, 0.0f);
            atomicAdd(ag + j, m);
        }
    }
}

// ================= conv2 edge messages: agg2[dst] += relu(h1[src] + ea @ e2_w + e2_b)
__global__ __launch_bounds__(256) void edge_msg2_kernel(
    const float* __restrict__ h1, const void* __restrict__ ei,
    const float* __restrict__ ea, const float* __restrict__ w,
    const float* __restrict__ b)
{
    __shared__ float sw[EDGE_DIM * HID];
    __shared__ float sb[HID];
    for (int i = threadIdx.x; i < EDGE_DIM * HID; i += blockDim.x) sw[i] = w[i];
    for (int i = threadIdx.x; i < HID; i += blockDim.x) sb[i] = b[i];
    __syncthreads();

    int is64   = g_is64;
    int lane   = threadIdx.x & 31;
    int warp   = (blockIdx.x * blockDim.x + threadIdx.x) >> 5;
    int nwarps = (gridDim.x * blockDim.x) >> 5;

    for (int e = warp; e < N_EDGES; e += nwarps) {
        int s, dd;
        load_edge(ei, e, is64, s, dd);
        float eav = (lane < EDGE_DIM) ? __ldg(&ea[(size_t)e * EDGE_DIM + lane]) : 0.0f;
        float a0 = __shfl_sync(0xffffffffu, eav, 0);
        float a1 = __shfl_sync(0xffffffffu, eav, 1);
        float a2 = __shfl_sync(0xffffffffu, eav, 2);
        float a3 = __shfl_sync(0xffffffffu, eav, 3);
        float a4 = __shfl_sync(0xffffffffu, eav, 4);
        float a5 = __shfl_sync(0xffffffffu, eav, 5);
        float a6 = __shfl_sync(0xffffffffu, eav, 6);
        const float4* xr = (const float4*)(h1 + (size_t)s * HID);  // 32 float4s
        float* ag = g_agg2 + (size_t)dd * HID;
        float4 xv = __ldg(xr + lane);
        int j0 = lane * 4;
        float m0, m1, m2, m3;
        {
            float c0 = sb[j0 + 0], c1 = sb[j0 + 1], c2 = sb[j0 + 2], c3 = sb[j0 + 3];
            c0 = fmaf(a0, sw[0 * HID + j0 + 0], c0); c1 = fmaf(a0, sw[0 * HID + j0 + 1], c1);
            c2 = fmaf(a0, sw[0 * HID + j0 + 2], c2); c3 = fmaf(a0, sw[0 * HID + j0 + 3], c3);
            c0 = fmaf(a1, sw[1 * HID + j0 + 0], c0); c1 = fmaf(a1, sw[1 * HID + j0 + 1], c1);
            c2 = fmaf(a1, sw[1 * HID + j0 + 2], c2); c3 = fmaf(a1, sw[1 * HID + j0 + 3], c3);
            c0 = fmaf(a2, sw[2 * HID + j0 + 0], c0); c1 = fmaf(a2, sw[2 * HID + j0 + 1], c1);
            c2 = fmaf(a2, sw[2 * HID + j0 + 2], c2); c3 = fmaf(a2, sw[2 * HID + j0 + 3], c3);
            c0 = fmaf(a3, sw[3 * HID + j0 + 0], c0); c1 = fmaf(a3, sw[3 * HID + j0 + 1], c1);
            c2 = fmaf(a3, sw[3 * HID + j0 + 2], c2); c3 = fmaf(a3, sw[3 * HID + j0 + 3], c3);
            c0 = fmaf(a4, sw[4 * HID + j0 + 0], c0); c1 = fmaf(a4, sw[4 * HID + j0 + 1], c1);
            c2 = fmaf(a4, sw[4 * HID + j0 + 2], c2); c3 = fmaf(a4, sw[4 * HID + j0 + 3], c3);
            c0 = fmaf(a5, sw[5 * HID + j0 + 0], c0); c1 = fmaf(a5, sw[5 * HID + j0 + 1], c1);
            c2 = fmaf(a5, sw[5 * HID + j0 + 2], c2); c3 = fmaf(a5, sw[5 * HID + j0 + 3], c3);
            c0 = fmaf(a6, sw[6 * HID + j0 + 0], c0); c1 = fmaf(a6, sw[6 * HID + j0 + 1], c1);
            c2 = fmaf(a6, sw[6 * HID + j0 + 2], c2); c3 = fmaf(a6, sw[6 * HID + j0 + 3], c3);
            m0 = fmaxf(xv.x + c0, 0.0f);
            m1 = fmaxf(xv.y + c1, 0.0f);
            m2 = fmaxf(xv.z + c2, 0.0f);
            m3 = fmaxf(xv.w + c3, 0.0f);
        }
        atomicAdd(ag + j0 + 0, m0);
        atomicAdd(ag + j0 + 1, m1);
        atomicAdd(ag + j0 + 2, m2);
        atomicAdd(ag + j0 + 3, m3);
    }
}

// ================= SGEMM: C[M,128] = relu((A (+A2)) @ B[K,128] + bias)
// 128x128 block tile, BK=8, 256 threads, 8x8 micro-tile, double-buffered smem.
__global__ __launch_bounds__(256) void gemm128_kernel(
    const float* __restrict__ A, const float* __restrict__ A2,
    const float* __restrict__ B, const float* __restrict__ bias,
    float* __restrict__ C, int M, int K)
{
    __shared__ __align__(16) float As[2][8][132];
    __shared__ __align__(16) float Bs[2][8][128];
    int tid = threadIdx.x;
    int tx = tid & 15, ty = tid >> 4;
    int mBase = blockIdx.x * 128;
    bool vecA = ((K & 7) == 0);

    float acc[8][8];
    #pragma unroll
    for (int i = 0; i < 8; i++)
        #pragma unroll
        for (int j = 0; j < 8; j++) acc[i][j] = 0.0f;

    // ---- load tile 0 directly into buffer 0 ----
    {
        if (vecA) {
            int m = tid >> 1, k4 = (tid & 1) * 4;
            int gm = mBase + m;
            float4 v = make_float4(0.0f, 0.0f, 0.0f, 0.0f);
            if (gm < M) {
                size_t idx = (size_t)gm * K + k4;
                v = *(const float4*)(A + idx);
                if (A2) {
                    float4 v2 = *(const float4*)(A2 + idx);
                    v.x += v2.x; v.y += v2.y; v.z += v2.z; v.w += v2.w;
                }
            }
            As[0][k4 + 0][m] = v.x; As[0][k4 + 1][m] = v.y;
            As[0][k4 + 2][m] = v.z; As[0][k4 + 3][m] = v.w;
        } else {
            #pragma unroll
            for (int i = 0; i < 4; i++) {
                int l = tid + 256 * i;
                int m = l >> 3, kk = l & 7;
                int gm = mBase + m, gk = kk;
                float v = 0.0f;
                if (gm < M && gk < K) {
                    size_t idx = (size_t)gm * K + gk;
                    v = __ldg(A + idx);
                    if (A2) v += __ldg(A2 + idx);
                }
                As[0][kk][m] = v;
            }
        }
        int kk = tid >> 5, j4 = (tid & 31) * 4;
        float4 v = make_float4(0.0f, 0.0f, 0.0f, 0.0f);
        if (kk < K) v = *(const float4*)(B + (size_t)kk * 128 + j4);
        *(float4*)&Bs[0][kk][j4] = v;
    }
    __syncthreads();

    int buf = 0;
    for (int k0 = 0; k0 < K; k0 += 8) {
        bool hasNext = (k0 + 8) < K;
        // ---- prefetch tile k0+8 into registers ----
        float4 aP = make_float4(0.0f, 0.0f, 0.0f, 0.0f);
        float aPs[4] = {0.0f, 0.0f, 0.0f, 0.0f};
        float4 bP = make_float4(0.0f, 0.0f, 0.0f, 0.0f);
        if (hasNext) {
            int kn = k0 + 8;
            if (vecA) {
                int m = tid >> 1, k4 = (tid & 1) * 4;
                int gm = mBase + m;
                if (gm < M) {
                    size_t idx = (size_t)gm * K + (kn + k4);
                    aP = *(const float4*)(A + idx);
                    if (A2) {
                        float4 v2 = *(const float4*)(A2 + idx);
                        aP.x += v2.x; aP.y += v2.y; aP.z += v2.z; aP.w += v2.w;
                    }
                }
            } else {
                #pragma unroll
                for (int i = 0; i < 4; i++) {
                    int l = tid + 256 * i;
                    int m = l >> 3, kk = l & 7;
                    int gm = mBase + m, gk = kn + kk;
                    if (gm < M && gk < K) {
                        size_t idx = (size_t)gm * K + gk;
                        aPs[i] = __ldg(A + idx);
                        if (A2) aPs[i] += __ldg(A2 + idx);
                    }
                }
            }
            int kk = tid >> 5, j4 = (tid & 31) * 4;
            int gk = kn + kk;
            if (gk < K) bP = *(const float4*)(B + (size_t)gk * 128 + j4);
        }
        // ---- compute on current buffer ----
        #pragma unroll
        for (int kk = 0; kk < 8; kk++) {
            float4 av0 = *(const float4*)&As[buf][kk][ty * 4];
            float4 av1 = *(const float4*)&As[buf][kk][64 + ty * 4];
            float4 bv0 = *(const float4*)&Bs[buf][kk][tx * 4];
            float4 bv1 = *(const float4*)&Bs[buf][kk][64 + tx * 4];
            float a[8] = {av0.x, av0.y, av0.z, av0.w, av1.x, av1.y, av1.z, av1.w};
            float b[8] = {bv0.x, bv0.y, bv0.z, bv0.w, bv1.x, bv1.y, bv1.z, bv1.w};
            #pragma unroll
            for (int i = 0; i < 8; i++)
                #pragma unroll
                for (int j = 0; j < 8; j++)
                    acc[i][j] = fmaf(a[i], b[j], acc[i][j]);
        }
        // ---- store prefetch into the other buffer ----
        if (hasNext) {
            int nb = buf ^ 1;
            if (vecA) {
                int m = tid >> 1, k4 = (tid & 1) * 4;
                As[nb][k4 + 0][m] = aP.x; As[nb][k4 + 1][m] = aP.y;
                As[nb][k4 + 2][m] = aP.z; As[nb][k4 + 3][m] = aP.w;
            } else {
                #pragma unroll
                for (int i = 0; i < 4; i++) {
                    int l = tid + 256 * i;
                    int m = l >> 3, kk = l & 7;
                    As[nb][kk][m] = aPs[i];
                }
            }
            int kk = tid >> 5, j4 = (tid & 31) * 4;
            *(float4*)&Bs[nb][kk][j4] = bP;
        }
        __syncthreads();
        buf ^= 1;
    }

    #pragma unroll
    for (int i = 0; i < 8; i++) {
        int rm = (i < 4) ? (ty * 4 + i) : (64 + ty * 4 + i - 4);
        int gr = mBase + rm;
        if (gr >= M) continue;
        #pragma unroll
        for (int j = 0; j < 8; j++) {
            int cn = (j < 4) ? (tx * 4 + j) : (64 + tx * 4 + j - 4);
            float v = fmaxf(acc[i][j] + bias[cn], 0.0f);
            C[(size_t)gr * 128 + cn] = v;
        }
    }
}

// ================= edge MLP: out[e,2] = relu([h2[src],h2[dst],ea] @ W1 + b1) @ W2 + b2
__global__ __launch_bounds__(256) void edge_out_kernel(
    const float* __restrict__ h2, const void* __restrict__ ei,
    const float* __restrict__ ea, const float* __restrict__ W1,
    const float* __restrict__ b1, const float* __restrict__ W2,
    const float* __restrict__ b2, float* __restrict__ out)
{
    __shared__ __align__(16) float As[2][8][132];
    __shared__ __align__(16) float Bs[2][8][128];
    __shared__ int ssrc[128], sdst[128];
    __shared__ float sb1[128];
    __shared__ float sw2[256];
    __shared__ float sacc[128][2];

    int tid = threadIdx.x;
    int tx = tid & 15, ty = tid >> 4;
    int eBase = blockIdx.x * 128;
    int is64 = g_is64;

    for (int i = tid; i < 128; i += 256) {
        int e = eBase + i;
        int s = 0, dd = 0;
        if (e < N_EDGES) load_edge(ei, e, is64, s, dd);
        ssrc[i] = s;
        sdst[i] = dd;
        sb1[i] = b1[i];
        sacc[i][0] = 0.0f;
        sacc[i][1] = 0.0f;
    }
    for (int i = tid; i < 256; i += 256) sw2[i] = W2[i];
    __syncthreads();

    float acc[8][8];
    #pragma unroll
    for (int i = 0; i < 8; i++)
        #pragma unroll
        for (int j = 0; j < 8; j++) acc[i][j] = 0.0f;

    // ---- load tile 0 into buffer 0 ----
    {
        #pragma unroll
        for (int i = 0; i < 4; i++) {
            int l = tid + 256 * i;
            int m = l >> 3, kk = l & 7;
            int e = eBase + m;
            float v = 0.0f;
            if (e < N_EDGES)  // kk < 8 <= 128, always the src segment
                v = __ldg(&h2[(size_t)ssrc[m] * 128 + kk]);
            As[0][kk][m] = v;
        }
        int kk = tid >> 5, j4 = (tid & 31) * 4;
        float4 v = *(const float4*)(W1 + (size_t)kk * 128 + j4);
        *(float4*)&Bs[0][kk][j4] = v;
    }
    __syncthreads();

    int buf = 0;
    for (int k0 = 0; k0 < EIN; k0 += 8) {
        bool hasNext = (k0 + 8) < EIN;
        // ---- prefetch tile k0+8 into registers ----
        float aPs[4] = {0.0f, 0.0f, 0.0f, 0.0f};
        float4 bP = make_float4(0.0f, 0.0f, 0.0f, 0.0f);
        if (hasNext) {
            int kn = k0 + 8;
            #pragma unroll
            for (int i = 0; i < 4; i++) {
                int l = tid + 256 * i;
                int m = l >> 3, kk = l & 7;
                int k = kn + kk;
                int e = eBase + m;
                if (k < EIN && e < N_EDGES) {
                    if (k < 128)      aPs[i] = __ldg(&h2[(size_t)ssrc[m] * 128 + k]);
                    else if (k < 256) aPs[i] = __ldg(&h2[(size_t)sdst[m] * 128 + (k - 128)]);
                    else              aPs[i] = __ldg(&ea[(size_t)e * EDGE_DIM + (k - 256)]);
                }
            }
            int kk = tid >> 5, j4 = (tid & 31) * 4;
            int k = kn + kk;
            if (k < EIN) bP = *(const float4*)(W1 + (size_t)k * 128 + j4);
        }
        // ---- compute on current buffer ----
        #pragma unroll
        for (int kk = 0; kk < 8; kk++) {
            float4 av0 = *(const float4*)&As[buf][kk][ty * 4];
            float4 av1 = *(const float4*)&As[buf][kk][64 + ty * 4];
            float4 bv0 = *(const float4*)&Bs[buf][kk][tx * 4];
            float4 bv1 = *(const float4*)&Bs[buf][kk][64 + tx * 4];
            float a[8] = {av0.x, av0.y, av0.z, av0.w, av1.x, av1.y, av1.z, av1.w};
            float b[8] = {bv0.x, bv0.y, bv0.z, bv0.w, bv1.x, bv1.y, bv1.z, bv1.w};
            #pragma unroll
            for (int i = 0; i < 8; i++)
                #pragma unroll
                for (int j = 0; j < 8; j++)
                    acc[i][j] = fmaf(a[i], b[j], acc[i][j]);
        }
        // ---- store prefetch into the other buffer ----
        if (hasNext) {
            int nb = buf ^ 1;
            #pragma unroll
            for (int i = 0; i < 4; i++) {
                int l = tid + 256 * i;
                int m = l >> 3, kk = l & 7;
                As[nb][kk][m] = aPs[i];
            }
            int kk = tid >> 5, j4 = (tid & 31) * 4;
            *(float4*)&Bs[nb][kk][j4] = bP;
        }
        __syncthreads();
        buf ^= 1;
    }

    // fused second layer: z = relu(acc + b1); partial out = z @ W2, reduced in shared
    #pragma unroll
    for (int i = 0; i < 8; i++) {
        int rm = (i < 4) ? (ty * 4 + i) : (64 + ty * 4 + i - 4);
        float p0 = 0.0f, p1 = 0.0f;
        #pragma unroll
        for (int j = 0; j < 8; j++) {
            int cn = (j < 4) ? (tx * 4 + j) : (64 + tx * 4 + j - 4);
            float z = fmaxf(acc[i][j] + sb1[cn], 0.0f);
            p0 = fmaf(z, sw2[cn * 2 + 0], p0);
            p1 = fmaf(z, sw2[cn * 2 + 1], p1);
        }
        atomicAdd(&sacc[rm][0], p0);
        atomicAdd(&sacc[rm][1], p1);
    }
    __syncthreads();

    float bb0 = b2[0], bb1 = b2[1];
    for (int i = tid; i < 128; i += 256) {
        int e = eBase + i;
        if (e < N_EDGES) {
            out[(size_t)e * 2 + 0] = sacc[i][0] + bb0;
            out[(size_t)e * 2 + 1] = sacc[i][1] + bb1;
        }
    }
}

extern "C" void kernel_launch(void* const* d_in, const int* in_sizes, int n_in,
                              void* d_out, int out_size)
{
    const float* x     = (const float*)d_in[0];
    const void*  ei    = d_in[1];   // int32 or int64 — detected on device
    const float* ea    = (const float*)d_in[2];
    const float* e1_w  = (const float*)d_in[3];
    const float* e1_b  = (const float*)d_in[4];
    const float* m1_w1 = (const float*)d_in[5];
    const float* m1_b1 = (const float*)d_in[6];
    const float* m1_w2 = (const float*)d_in[7];
    const float* m1_b2 = (const float*)d_in[8];
    const float* e2_w  = (const float*)d_in[9];
    const float* e2_b  = (const float*)d_in[10];
    const float* m2_w1 = (const float*)d_in[11];
    const float* m2_b1 = (const float*)d_in[12];
    const float* m2_w2 = (const float*)d_in[13];
    const float* m2_b2 = (const float*)d_in[14];
    const float* em_w1 = (const float*)d_in[15];
    const float* em_b1 = (const float*)d_in[16];
    const float* em_w2 = (const float*)d_in[17];
    const float* em_b2 = (const float*)d_in[18];
    float* out = (float*)d_out;

    void *agg1p = nullptr, *agg2p = nullptr, *tp = nullptr, *h1p = nullptr, *h2p = nullptr;
    cudaGetSymbolAddress(&agg1p, g_agg1);
    cudaGetSymbolAddress(&agg2p, g_agg2);
    cudaGetSymbolAddress(&tp, g_t);
    cudaGetSymbolAddress(&h1p, g_h1);
    cudaGetSymbolAddress(&h2p, g_h2);
    float* agg1 = (float*)agg1p;
    float* agg2 = (float*)agg2p;
    float* tbuf = (float*)tp;
    float* h1   = (float*)h1p;
    float* h2   = (float*)h2p;

    cudaMemsetAsync(agg1p, 0, sizeof(float) * (size_t)N_NODES * NODE_IN, 0);
    cudaMemsetAsync(agg2p, 0, sizeof(float) * (size_t)N_NODES * HID, 0);

    const int gblocks = (N_NODES + 127) / 128;   // 782
    const int eblocks = (N_EDGES + 127) / 128;   // 4688

    detect_idx_kernel<<<1, 32>>>((const long long*)ei);
    // conv1
    edge_msg1_kernel<<<1480, 256>>>(x, ei, ea, e1_w, e1_b);
    gemm128_kernel<<<gblocks, 256>>>(x, agg1, m1_w1, m1_b1, tbuf, N_NODES, NODE_IN);
    gemm128_kernel<<<gblocks, 256>>>(tbuf, nullptr, m1_w2, m1_b2, h1, N_NODES, HID);
    // conv2
    edge_msg2_kernel<<<1480, 256>>>(h1, ei, ea, e2_w, e2_b);
    gemm128_kernel<<<gblocks, 256>>>(h1, agg2, m2_w1, m2_b1, tbuf, N_NODES, HID);
    gemm128_kernel<<<gblocks, 256>>>(tbuf, nullptr, m2_w2, m2_b2, h2, N_NODES, HID);
    // edge MLP
    edge_out_kernel<<<eblocks, 256>>>(h2, ei, ea, em_w1, em_b1, em_w2, em_b2, out);
}

// round 16
// speedup vs baseline: 1.4937x; 1.4937x over previous
#include <cuda_runtime.h>
#include <stdint.h>

#define N_NODES 100000
#define N_EDGES 600000
#define NODE_IN 387
#define HID 128
#define EDGE_DIM 7
#define EIN 263  // 2*HID + EDGE_DIM

// -------- scratch (device globals; no allocation allowed) --------
__device__ float g_agg1[(size_t)N_NODES * NODE_IN];  // 154.8 MB; reused as P|Q later
__device__ float g_t   [(size_t)N_NODES * HID];      // 51.2 MB
__device__ float g_h1  [(size_t)N_NODES * HID];
__device__ float g_agg2[(size_t)N_NODES * HID];
__device__ float g_h2  [(size_t)N_NODES * HID];
__device__ int   g_is64;  // 1 if edge_index is int64, 0 if int32

// Detect edge_index dtype from data: int64 words are valid indices < N_NODES;
// int32 data read as int64 packs two indices and exceeds N_NODES w.h.p.
__global__ void detect_idx_kernel(const long long* __restrict__ ei)
{
    if (threadIdx.x == 0 && blockIdx.x == 0) {
        int is64 = 1;
        #pragma unroll
        for (int i = 0; i < 16; i++) {
            long long v = ei[i];
            if (v < 0 || v >= (long long)N_NODES) is64 = 0;
        }
        g_is64 = is64;
    }
}

__device__ __forceinline__ void load_edge(const void* ei, int e, int is64, int& s, int& dd)
{
    if (is64) {
        const long long* p = (const long long*)ei;
        s  = (int)__ldg(&p[e]);
        dd = (int)__ldg(&p[N_EDGES + e]);
    } else {
        const int* p = (const int*)ei;
        s  = __ldg(&p[e]);
        dd = __ldg(&p[N_EDGES + e]);
    }
}

// ================= conv1 edge messages: agg1[dst] += relu(x[src] + ea @ e1_w + e1_b)
__global__ __launch_bounds__(256) void edge_msg1_kernel(
    const float* __restrict__ x, const void* __restrict__ ei,
    const float* __restrict__ ea, const float* __restrict__ w,
    const float* __restrict__ b)
{
    __shared__ float sw[EDGE_DIM * NODE_IN];
    __shared__ float sb[NODE_IN];
    for (int i = threadIdx.x; i < EDGE_DIM * NODE_IN; i += blockDim.x) sw[i] = w[i];
    for (int i = threadIdx.x; i < NODE_IN; i += blockDim.x) sb[i] = b[i];
    __syncthreads();

    int is64   = g_is64;
    int lane   = threadIdx.x & 31;
    int warp   = (blockIdx.x * blockDim.x + threadIdx.x) >> 5;
    int nwarps = (gridDim.x * blockDim.x) >> 5;

    for (int e = warp; e < N_EDGES; e += nwarps) {
        int s, dd;
        load_edge(ei, e, is64, s, dd);
        float eav = (lane < EDGE_DIM) ? __ldg(&ea[(size_t)e * EDGE_DIM + lane]) : 0.0f;
        float a0 = __shfl_sync(0xffffffffu, eav, 0);
        float a1 = __shfl_sync(0xffffffffu, eav, 1);
        float a2 = __shfl_sync(0xffffffffu, eav, 2);
        float a3 = __shfl_sync(0xffffffffu, eav, 3);
        float a4 = __shfl_sync(0xffffffffu, eav, 4);
        float a5 = __shfl_sync(0xffffffffu, eav, 5);
        float a6 = __shfl_sync(0xffffffffu, eav, 6);
        const float* xr = x + (size_t)s * NODE_IN;
        float* ag = g_agg1 + (size_t)dd * NODE_IN;
        #pragma unroll 4
        for (int j = lane; j < NODE_IN; j += 32) {
            float c = sb[j];
            c = fmaf(a0, sw[0 * NODE_IN + j], c);
            c = fmaf(a1, sw[1 * NODE_IN + j], c);
            c = fmaf(a2, sw[2 * NODE_IN + j], c);
            c = fmaf(a3, sw[3 * NODE_IN + j], c);
            c = fmaf(a4, sw[4 * NODE_IN + j], c);
            c = fmaf(a5, sw[5 * NODE_IN + j], c);
            c = fmaf(a6, sw[6 * NODE_IN + j], c);
            float m = fmaxf(__ldg(xr + j) + c, 0.0f);
            atomicAdd(ag + j, m);
        }
    }
}

// ================= conv2 edge messages: agg2[dst] += relu(h1[src] + ea @ e2_w + e2_b)
__global__ __launch_bounds__(256) void edge_msg2_kernel(
    const float* __restrict__ h1, const void* __restrict__ ei,
    const float* __restrict__ ea, const float* __restrict__ w,
    const float* __restrict__ b)
{
    __shared__ float sw[EDGE_DIM * HID];
    __shared__ float sb[HID];
    for (int i = threadIdx.x; i < EDGE_DIM * HID; i += blockDim.x) sw[i] = w[i];
    for (int i = threadIdx.x; i < HID; i += blockDim.x) sb[i] = b[i];
    __syncthreads();

    int is64   = g_is64;
    int lane   = threadIdx.x & 31;
    int warp   = (blockIdx.x * blockDim.x + threadIdx.x) >> 5;
    int nwarps = (gridDim.x * blockDim.x) >> 5;

    for (int e = warp; e < N_EDGES; e += nwarps) {
        int s, dd;
        load_edge(ei, e, is64, s, dd);
        float eav = (lane < EDGE_DIM) ? __ldg(&ea[(size_t)e * EDGE_DIM + lane]) : 0.0f;
        float a0 = __shfl_sync(0xffffffffu, eav, 0);
        float a1 = __shfl_sync(0xffffffffu, eav, 1);
        float a2 = __shfl_sync(0xffffffffu, eav, 2);
        float a3 = __shfl_sync(0xffffffffu, eav, 3);
        float a4 = __shfl_sync(0xffffffffu, eav, 4);
        float a5 = __shfl_sync(0xffffffffu, eav, 5);
        float a6 = __shfl_sync(0xffffffffu, eav, 6);
        const float4* xr = (const float4*)(h1 + (size_t)s * HID);  // 32 float4s
        float* ag = g_agg2 + (size_t)dd * HID;
        float4 xv = __ldg(xr + lane);
        int j0 = lane * 4;
        float m0, m1, m2, m3;
        {
            float c0 = sb[j0 + 0], c1 = sb[j0 + 1], c2 = sb[j0 + 2], c3 = sb[j0 + 3];
            c0 = fmaf(a0, sw[0 * HID + j0 + 0], c0); c1 = fmaf(a0, sw[0 * HID + j0 + 1], c1);
            c2 = fmaf(a0, sw[0 * HID + j0 + 2], c2); c3 = fmaf(a0, sw[0 * HID + j0 + 3], c3);
            c0 = fmaf(a1, sw[1 * HID + j0 + 0], c0); c1 = fmaf(a1, sw[1 * HID + j0 + 1], c1);
            c2 = fmaf(a1, sw[1 * HID + j0 + 2], c2); c3 = fmaf(a1, sw[1 * HID + j0 + 3], c3);
            c0 = fmaf(a2, sw[2 * HID + j0 + 0], c0); c1 = fmaf(a2, sw[2 * HID + j0 + 1], c1);
            c2 = fmaf(a2, sw[2 * HID + j0 + 2], c2); c3 = fmaf(a2, sw[2 * HID + j0 + 3], c3);
            c0 = fmaf(a3, sw[3 * HID + j0 + 0], c0); c1 = fmaf(a3, sw[3 * HID + j0 + 1], c1);
            c2 = fmaf(a3, sw[3 * HID + j0 + 2], c2); c3 = fmaf(a3, sw[3 * HID + j0 + 3], c3);
            c0 = fmaf(a4, sw[4 * HID + j0 + 0], c0); c1 = fmaf(a4, sw[4 * HID + j0 + 1], c1);
            c2 = fmaf(a4, sw[4 * HID + j0 + 2], c2); c3 = fmaf(a4, sw[4 * HID + j0 + 3], c3);
            c0 = fmaf(a5, sw[5 * HID + j0 + 0], c0); c1 = fmaf(a5, sw[5 * HID + j0 + 1], c1);
            c2 = fmaf(a5, sw[5 * HID + j0 + 2], c2); c3 = fmaf(a5, sw[5 * HID + j0 + 3], c3);
            c0 = fmaf(a6, sw[6 * HID + j0 + 0], c0); c1 = fmaf(a6, sw[6 * HID + j0 + 1], c1);
            c2 = fmaf(a6, sw[6 * HID + j0 + 2], c2); c3 = fmaf(a6, sw[6 * HID + j0 + 3], c3);
            m0 = fmaxf(xv.x + c0, 0.0f);
            m1 = fmaxf(xv.y + c1, 0.0f);
            m2 = fmaxf(xv.z + c2, 0.0f);
            m3 = fmaxf(xv.w + c3, 0.0f);
        }
        atomicAdd(ag + j0 + 0, m0);
        atomicAdd(ag + j0 + 1, m1);
        atomicAdd(ag + j0 + 2, m2);
        atomicAdd(ag + j0 + 3, m3);
    }
}

// ================= SGEMM: C[M,128] = act ? relu((A+A2)@B + bias) : (A+A2)@B
// 128x128 block tile, BK=8, 256 threads, 8x8 micro-tile, double-buffered smem.
__global__ __launch_bounds__(256) void gemm128_kernel(
    const float* __restrict__ A, const float* __restrict__ A2,
    const float* __restrict__ B, const float* __restrict__ bias,
    float* __restrict__ C, int M, int K, int act)
{
    __shared__ __align__(16) float As[2][8][132];
    __shared__ __align__(16) float Bs[2][8][128];
    int tid = threadIdx.x;
    int tx = tid & 15, ty = tid >> 4;
    int mBase = blockIdx.x * 128;
    bool vecA = ((K & 7) == 0);

    float acc[8][8];
    #pragma unroll
    for (int i = 0; i < 8; i++)
        #pragma unroll
        for (int j = 0; j < 8; j++) acc[i][j] = 0.0f;

    // ---- load tile 0 directly into buffer 0 ----
    {
        if (vecA) {
            int m = tid >> 1, k4 = (tid & 1) * 4;
            int gm = mBase + m;
            float4 v = make_float4(0.0f, 0.0f, 0.0f, 0.0f);
            if (gm < M) {
                size_t idx = (size_t)gm * K + k4;
                v = *(const float4*)(A + idx);
                if (A2) {
                    float4 v2 = *(const float4*)(A2 + idx);
                    v.x += v2.x; v.y += v2.y; v.z += v2.z; v.w += v2.w;
                }
            }
            As[0][k4 + 0][m] = v.x; As[0][k4 + 1][m] = v.y;
            As[0][k4 + 2][m] = v.z; As[0][k4 + 3][m] = v.w;
        } else {
            #pragma unroll
            for (int i = 0; i < 4; i++) {
                int l = tid + 256 * i;
                int m = l >> 3, kk = l & 7;
                int gm = mBase + m, gk = kk;
                float v = 0.0f;
                if (gm < M && gk < K) {
                    size_t idx = (size_t)gm * K + gk;
                    v = __ldg(A + idx);
                    if (A2) v += __ldg(A2 + idx);
                }
                As[0][kk][m] = v;
            }
        }
        int kk = tid >> 5, j4 = (tid & 31) * 4;
        float4 v = make_float4(0.0f, 0.0f, 0.0f, 0.0f);
        if (kk < K) v = *(const float4*)(B + (size_t)kk * 128 + j4);
        *(float4*)&Bs[0][kk][j4] = v;
    }
    __syncthreads();

    int buf = 0;
    for (int k0 = 0; k0 < K; k0 += 8) {
        bool hasNext = (k0 + 8) < K;
        float4 aP = make_float4(0.0f, 0.0f, 0.0f, 0.0f);
        float aPs[4] = {0.0f, 0.0f, 0.0f, 0.0f};
        float4 bP = make_float4(0.0f, 0.0f, 0.0f, 0.0f);
        if (hasNext) {
            int kn = k0 + 8;
            if (vecA) {
                int m = tid >> 1, k4 = (tid & 1) * 4;
                int gm = mBase + m;
                if (gm < M) {
                    size_t idx = (size_t)gm * K + (kn + k4);
                    aP = *(const float4*)(A + idx);
                    if (A2) {
                        float4 v2 = *(const float4*)(A2 + idx);
                        aP.x += v2.x; aP.y += v2.y; aP.z += v2.z; aP.w += v2.w;
                    }
                }
            } else {
                #pragma unroll
                for (int i = 0; i < 4; i++) {
                    int l = tid + 256 * i;
                    int m = l >> 3, kk = l & 7;
                    int gm = mBase + m, gk = kn + kk;
                    if (gm < M && gk < K) {
                        size_t idx = (size_t)gm * K + gk;
                        aPs[i] = __ldg(A + idx);
                        if (A2) aPs[i] += __ldg(A2 + idx);
                    }
                }
            }
            int kk = tid >> 5, j4 = (tid & 31) * 4;
            int gk = kn + kk;
            if (gk < K) bP = *(const float4*)(B + (size_t)gk * 128 + j4);
        }
        #pragma unroll
        for (int kk = 0; kk < 8; kk++) {
            float4 av0 = *(const float4*)&As[buf][kk][ty * 4];
            float4 av1 = *(const float4*)&As[buf][kk][64 + ty * 4];
            float4 bv0 = *(const float4*)&Bs[buf][kk][tx * 4];
            float4 bv1 = *(const float4*)&Bs[buf][kk][64 + tx * 4];
            float a[8] = {av0.x, av0.y, av0.z, av0.w, av1.x, av1.y, av1.z, av1.w};
            float b[8] = {bv0.x, bv0.y, bv0.z, bv0.w, bv1.x, bv1.y, bv1.z, bv1.w};
            #pragma unroll
            for (int i = 0; i < 8; i++)
                #pragma unroll
                for (int j = 0; j < 8; j++)
                    acc[i][j] = fmaf(a[i], b[j], acc[i][j]);
        }
        if (hasNext) {
            int nb = buf ^ 1;
            if (vecA) {
                int m = tid >> 1, k4 = (tid & 1) * 4;
                As[nb][k4 + 0][m] = aP.x; As[nb][k4 + 1][m] = aP.y;
                As[nb][k4 + 2][m] = aP.z; As[nb][k4 + 3][m] = aP.w;
            } else {
                #pragma unroll
                for (int i = 0; i < 4; i++) {
                    int l = tid + 256 * i;
                    int m = l >> 3, kk = l & 7;
                    As[nb][kk][m] = aPs[i];
                }
            }
            int kk = tid >> 5, j4 = (tid & 31) * 4;
            *(float4*)&Bs[nb][kk][j4] = bP;
        }
        __syncthreads();
        buf ^= 1;
    }

    #pragma unroll
    for (int i = 0; i < 8; i++) {
        int rm = (i < 4) ? (ty * 4 + i) : (64 + ty * 4 + i - 4);
        int gr = mBase + rm;
        if (gr >= M) continue;
        #pragma unroll
        for (int j = 0; j < 8; j++) {
            int cn = (j < 4) ? (tx * 4 + j) : (64 + tx * 4 + j - 4);
            float v = acc[i][j];
            if (act) v = fmaxf(v + bias[cn], 0.0f);
            C[(size_t)gr * 128 + cn] = v;
        }
    }
}

// ================= edge final: out[e,:] = relu(P[src]+Q[dst]+ea@W1c+b1) @ W2 + b2
// P = h2@W1[0:128,:], Q = h2@W1[128:256,:], W1c = W1[256:263,:]. Warp per edge.
__global__ __launch_bounds__(256) void edge_final_kernel(
    const float* __restrict__ P, const float* __restrict__ Q,
    const void* __restrict__ ei, const float* __restrict__ ea,
    const float* __restrict__ W1, const float* __restrict__ b1,
    const float* __restrict__ W2, const float* __restrict__ b2,
    float* __restrict__ out)
{
    __shared__ float swc[EDGE_DIM * HID];  // W1 rows 256..262
    __shared__ float sb1[HID];
    __shared__ float sw2[2 * HID];
    for (int i = threadIdx.x; i < EDGE_DIM * HID; i += blockDim.x)
        swc[i] = W1[(size_t)(256 + (i >> 7)) * HID + (i & 127)];
    for (int i = threadIdx.x; i < HID; i += blockDim.x) sb1[i] = b1[i];
    for (int i = threadIdx.x; i < 2 * HID; i += blockDim.x) sw2[i] = W2[i];
    __syncthreads();

    int is64   = g_is64;
    int lane   = threadIdx.x & 31;
    int warp   = (blockIdx.x * blockDim.x + threadIdx.x) >> 5;
    int nwarps = (gridDim.x * blockDim.x) >> 5;
    float bb0 = __ldg(&b2[0]), bb1 = __ldg(&b2[1]);

    for (int e = warp; e < N_EDGES; e += nwarps) {
        int s, dd;
        load_edge(ei, e, is64, s, dd);
        float eav = (lane < EDGE_DIM) ? __ldg(&ea[(size_t)e * EDGE_DIM + lane]) : 0.0f;
        float a0 = __shfl_sync(0xffffffffu, eav, 0);
        float a1 = __shfl_sync(0xffffffffu, eav, 1);
        float a2 = __shfl_sync(0xffffffffu, eav, 2);
        float a3 = __shfl_sync(0xffffffffu, eav, 3);
        float a4 = __shfl_sync(0xffffffffu, eav, 4);
        float a5 = __shfl_sync(0xffffffffu, eav, 5);
        float a6 = __shfl_sync(0xffffffffu, eav, 6);
        float4 pv = __ldg((const float4*)(P + (size_t)s * HID) + lane);
        float4 qv = __ldg((const float4*)(Q + (size_t)dd * HID) + lane);
        int j0 = lane * 4;
        float z0, z1, z2, z3;
        {
            float c0 = sb1[j0 + 0], c1 = sb1[j0 + 1], c2 = sb1[j0 + 2], c3 = sb1[j0 + 3];
            c0 = fmaf(a0, swc[0 * HID + j0 + 0], c0); c1 = fmaf(a0, swc[0 * HID + j0 + 1], c1);
            c2 = fmaf(a0, swc[0 * HID + j0 + 2], c2); c3 = fmaf(a0, swc[0 * HID + j0 + 3], c3);
            c0 = fmaf(a1, swc[1 * HID + j0 + 0], c0); c1 = fmaf(a1, swc[1 * HID + j0 + 1], c1);
            c2 = fmaf(a1, swc[1 * HID + j0 + 2], c2); c3 = fmaf(a1, swc[1 * HID + j0 + 3], c3);
            c0 = fmaf(a2, swc[2 * HID + j0 + 0], c0); c1 = fmaf(a2, swc[2 * HID + j0 + 1], c1);
            c2 = fmaf(a2, swc[2 * HID + j0 + 2], c2); c3 = fmaf(a2, swc[2 * HID + j0 + 3], c3);
            c0 = fmaf(a3, swc[3 * HID + j0 + 0], c0); c1 = fmaf(a3, swc[3 * HID + j0 + 1], c1);
            c2 = fmaf(a3, swc[3 * HID + j0 + 2], c2); c3 = fmaf(a3, swc[3 * HID + j0 + 3], c3);
            c0 = fmaf(a4, swc[4 * HID + j0 + 0], c0); c1 = fmaf(a4, swc[4 * HID + j0 + 1], c1);
            c2 = fmaf(a4, swc[4 * HID + j0 + 2], c2); c3 = fmaf(a4, swc[4 * HID + j0 + 3], c3);
            c0 = fmaf(a5, swc[5 * HID + j0 + 0], c0); c1 = fmaf(a5, swc[5 * HID + j0 + 1], c1);
            c2 = fmaf(a5, swc[5 * HID + j0 + 2], c2); c3 = fmaf(a5, swc[5 * HID + j0 + 3], c3);
            c0 = fmaf(a6, swc[6 * HID + j0 + 0], c0); c1 = fmaf(a6, swc[6 * HID + j0 + 1], c1);
            c2 = fmaf(a6, swc[6 * HID + j0 + 2], c2); c3 = fmaf(a6, swc[6 * HID + j0 + 3], c3);
            z0 = fmaxf(pv.x + qv.x + c0, 0.0f);
            z1 = fmaxf(pv.y + qv.y + c1, 0.0f);
            z2 = fmaxf(pv.z + qv.z + c2, 0.0f);
            z3 = fmaxf(pv.w + qv.w + c3, 0.0f);
        }
        float p0 = z0 * sw2[(j0 + 0) * 2 + 0] + z1 * sw2[(j0 + 1) * 2 + 0]
                 + z2 * sw2[(j0 + 2) * 2 + 0] + z3 * sw2[(j0 + 3) * 2 + 0];
        float p1 = z0 * sw2[(j0 + 0) * 2 + 1] + z1 * sw2[(j0 + 1) * 2 + 1]
                 + z2 * sw2[(j0 + 2) * 2 + 1] + z3 * sw2[(j0 + 3) * 2 + 1];
        #pragma unroll
        for (int off = 16; off > 0; off >>= 1) {
            p0 += __shfl_down_sync(0xffffffffu, p0, off);
            p1 += __shfl_down_sync(0xffffffffu, p1, off);
        }
        if (lane == 0) {
            out[(size_t)e * 2 + 0] = p0 + bb0;
            out[(size_t)e * 2 + 1] = p1 + bb1;
        }
    }
}

extern "C" void kernel_launch(void* const* d_in, const int* in_sizes, int n_in,
                              void* d_out, int out_size)
{
    const float* x     = (const float*)d_in[0];
    const void*  ei    = d_in[1];   // int32 or int64 — detected on device
    const float* ea    = (const float*)d_in[2];
    const float* e1_w  = (const float*)d_in[3];
    const float* e1_b  = (const float*)d_in[4];
    const float* m1_w1 = (const float*)d_in[5];
    const float* m1_b1 = (const float*)d_in[6];
    const float* m1_w2 = (const float*)d_in[7];
    const float* m1_b2 = (const float*)d_in[8];
    const float* e2_w  = (const float*)d_in[9];
    const float* e2_b  = (const float*)d_in[10];
    const float* m2_w1 = (const float*)d_in[11];
    const float* m2_b1 = (const float*)d_in[12];
    const float* m2_w2 = (const float*)d_in[13];
    const float* m2_b2 = (const float*)d_in[14];
    const float* em_w1 = (const float*)d_in[15];
    const float* em_b1 = (const float*)d_in[16];
    const float* em_w2 = (const float*)d_in[17];
    const float* em_b2 = (const float*)d_in[18];
    float* out = (float*)d_out;

    void *agg1p = nullptr, *agg2p = nullptr, *tp = nullptr, *h1p = nullptr, *h2p = nullptr;
    cudaGetSymbolAddress(&agg1p, g_agg1);
    cudaGetSymbolAddress(&agg2p, g_agg2);
    cudaGetSymbolAddress(&tp, g_t);
    cudaGetSymbolAddress(&h1p, g_h1);
    cudaGetSymbolAddress(&h2p, g_h2);
    float* agg1 = (float*)agg1p;
    float* agg2 = (float*)agg2p;
    float* tbuf = (float*)tp;
    float* h1   = (float*)h1p;
    float* h2   = (float*)h2p;
    // After conv1, agg1 is dead: reuse it for P|Q (needs 2*N*HID = 102.4MB <= 154.8MB)
    float* P = agg1;
    float* Q = agg1 + (size_t)N_NODES * HID;

    cudaMemsetAsync(agg1p, 0, sizeof(float) * (size_t)N_NODES * NODE_IN, 0);
    cudaMemsetAsync(agg2p, 0, sizeof(float) * (size_t)N_NODES * HID, 0);

    const int gblocks = (N_NODES + 127) / 128;   // 782

    detect_idx_kernel<<<1, 32>>>((const long long*)ei);
    // conv1
    edge_msg1_kernel<<<1480, 256>>>(x, ei, ea, e1_w, e1_b);
    gemm128_kernel<<<gblocks, 256>>>(x, agg1, m1_w1, m1_b1, tbuf, N_NODES, NODE_IN, 1);
    gemm128_kernel<<<gblocks, 256>>>(tbuf, nullptr, m1_w2, m1_b2, h1, N_NODES, HID, 1);
    // conv2
    edge_msg2_kernel<<<1480, 256>>>(h1, ei, ea, e2_w, e2_b);
    gemm128_kernel<<<gblocks, 256>>>(h1, agg2, m2_w1, m2_b1, tbuf, N_NODES, HID, 1);
    gemm128_kernel<<<gblocks, 256>>>(tbuf, nullptr, m2_w2, m2_b2, h2, N_NODES, HID, 1);
    // edge MLP, restructured: P = h2@W1[0:128], Q = h2@W1[128:256] (raw, no act)
    gemm128_kernel<<<gblocks, 256>>>(h2, nullptr, em_w1, em_b1, P, N_NODES, HID, 0);
    gemm128_kernel<<<gblocks, 256>>>(h2, nullptr, em_w1 + (size_t)128 * HID, em_b1, Q, N_NODES, HID, 0);
    edge_final_kernel<<<1480, 256>>>(P, Q, ei, ea, em_w1, em_b1, em_w2, em_b2, out);
}